// round 11
// baseline (speedup 1.0000x reference)
#include <cuda_runtime.h>
#include <cuda_bf16.h>
#include <cstdint>

// Problem constants
#define NN      131072
#define FF      512
#define EE      2097152
#define DA      16
#define NPOOL   65536
#define FP      256
#define NB      65536       // buckets = pooled row (key >> 16)
#define MAXB    128         // max bucket size (Poisson mean 32)
#define NSLOT   ((unsigned)NB * MAXB)

// Output layout (float elements, single concatenated array)
#define X_OFF   0ull
#define EI_OFF  16777216ull
#define EA_OFF  (EI_OFF + 2ull*EE)
#define BP_OFF  (EA_OFF + (unsigned long long)EE*DA)

// ---------------- scratch ----------------------------------------------------
__device__ unsigned long long  g_bkt[NSLOT];   // 64 MB fixed slots: (key<<32)|edge
__device__ unsigned short      g_ms[NSLOT];    // 16 MB: head<<15 | lrank<<8 | slot
__device__ unsigned            g_cnt[NB];
__device__ unsigned            g_dcnt[NB];
__device__ unsigned            g_doff[NB];
__device__ unsigned            g_part[256];
__device__ unsigned            g_partoff[256];
__device__ unsigned            g_totalU;
__device__ unsigned            g_done;
__device__ unsigned            g_flag;
__device__ int                 g_is32;

// ---------------- helpers -----------------------------------------------------

__device__ __forceinline__ void xpool_chunk(unsigned t, const float* __restrict__ x,
                                            float* __restrict__ out) {
    if (t >= NPOOL * (FP / 2)) return;
    unsigned n  = t >> 7;
    unsigned fq = t & 127;
    const float4* r0 = (const float4*)(x + (size_t)(2 * n) * FF)     + fq;
    const float4* r1 = (const float4*)(x + (size_t)(2 * n + 1) * FF) + fq;
    float4 a = *r0, b = *r1;
    float2 o;
    o.x = 0.25f * ((a.x + a.y) + (b.x + b.y));
    o.y = 0.25f * ((a.z + a.w) + (b.z + b.w));
    *(float2*)(out + X_OFF + (size_t)n * FP + 2 * fq) = o;
}

// ---- warp-level bitonic sort on 32-bit items, zero barriers -----------------
template<int NR>
__device__ __forceinline__ void warp_bitonic32(unsigned (&v)[NR], unsigned lane) {
    const unsigned N = NR * 32;
#pragma unroll
    for (unsigned k = 2; k <= N; k <<= 1) {
#pragma unroll
        for (unsigned j = N >> 1; j > 0; j >>= 1) {
            if (j >= k) continue;   // compile-time pruned
            if (j >= 32) {
                unsigned rj = j >> 5;
#pragma unroll
                for (int r = 0; r < NR; r++) {
                    if ((r & (int)rj) == 0 && (r ^ (int)rj) < NR) {
                        int r2 = r ^ (int)rj;
                        unsigned ia = r * 32 + lane;
                        bool up = ((ia & k) == 0);
                        unsigned a = v[r], b = v[r2];
                        if ((a > b) == up) { v[r] = b; v[r2] = a; }
                    }
                }
            } else {
#pragma unroll
                for (int r = 0; r < NR; r++) {
                    unsigned i = r * 32 + lane;
                    unsigned x = v[r];
                    unsigned y = __shfl_xor_sync(~0u, x, j);
                    bool up = ((i & k) == 0);
                    bool keepmin = (((lane & j) == 0) == up);
                    v[r] = keepmin ? (x < y ? x : y) : (x > y ? x : y);
                }
            }
        }
    }
}

template<int NR>
__device__ __forceinline__ void sort_bucket(unsigned b, unsigned count, unsigned lane) {
    size_t start = (size_t)b * MAXB;
    unsigned v[NR];
#pragma unroll
    for (int r = 0; r < NR; r++) {
        unsigned i = r * 32 + lane;
        if (i < count) {
            unsigned key = (unsigned)(g_bkt[start + i] >> 32);
            v[r] = ((key & 0xFFFFu) << 7) | i;     // col<<7 | slot
        } else v[r] = 0xFFFFFFFFu;
    }
    warp_bitonic32<NR>(v, lane);

    unsigned mask[NR];
    unsigned prev_last = 0xFFFFFFFFu;
#pragma unroll
    for (int r = 0; r < NR; r++) {
        unsigned p = __shfl_up_sync(~0u, v[r], 1);
        unsigned last = __shfl_sync(~0u, v[r], 31);
        if (lane == 0) p = prev_last;
        unsigned i = r * 32 + lane;
        bool head = (i < count) && ((i == 0) || ((p >> 7) != (v[r] >> 7)));
        mask[r] = __ballot_sync(~0u, head);
        prev_last = last;
    }
    unsigned base = 0;
#pragma unroll
    for (int r = 0; r < NR; r++) {
        unsigned i = r * 32 + lane;
        if (i < count) {
            unsigned head = (mask[r] >> lane) & 1u;
            unsigned lr = base + __popc(mask[r] & ((1u << lane) - 1u));
            g_ms[start + i] = (unsigned short)((head << 15) | (lr << 8) | (v[r] & 0x7Fu));
        }
        base += __popc(mask[r]);
    }
    if (lane == 0) g_dcnt[b] = base;
}

// ---------------- kernels ----------------------------------------------------

// init: zero g_cnt + tickets; block 0 warp 0 sniffs edge_index dtype
__global__ __launch_bounds__(256) void k_init(const int2* __restrict__ ei) {
    unsigned i = blockIdx.x * 256 + threadIdx.x;
    g_cnt[i] = 0;
    if (i == 0) { g_done = 0; g_flag = 0; }
    if (blockIdx.x == 0 && threadIdx.x < 32) {
        unsigned lane = threadIdx.x;
        bool nz = false;
#pragma unroll
        for (int k = 0; k < 8; k++) nz |= (ei[lane * 8 + k].y != 0);
        unsigned m = __ballot_sync(~0u, nz);
        if (lane == 0) g_is32 = (m != 0) ? 1 : 0;
    }
}

// P1: pure scatter (8192 blocks) + 256 batch blocks
#define P1_MAIN 8192
#define P1_GRID (P1_MAIN + 256)
__global__ __launch_bounds__(256) void k_p1(const void* __restrict__ eiv,
                                            float* __restrict__ out) {
    unsigned bid = blockIdx.x;
    if (bid >= P1_MAIN) {                           // batch_pooled
        unsigned n = (bid - P1_MAIN) * 256 + threadIdx.x;
        if (n < NPOOL) out[BP_OFF + n] = (float)(n >> 10);
        return;
    }
    unsigned e = bid * 256 + threadIdx.x;
    unsigned r, c;
    if (g_is32) {
        const int* ei = (const int*)eiv;
        r = (unsigned)ei[e]; c = (unsigned)ei[EE + e];
    } else {
        const long long* ei = (const long long*)eiv;
        r = (unsigned)ei[e]; c = (unsigned)ei[EE + e];
    }
    unsigned key = ((r >> 1) << 16) | (c >> 1);
    unsigned b = key >> 16;
    unsigned pos = atomicAdd(&g_cnt[b], 1u);
    if (pos < MAXB)
        g_bkt[(size_t)b * MAXB + pos] = ((unsigned long long)key << 32) | (unsigned)e;
}

// P2: 1-in-5 blocks sort (8 buckets/block), 4-in-5 blocks do ALL of xpool (R6-proven)
#define P2_GRID (8192 * 5)
__global__ __launch_bounds__(256) void k_p2(const float* __restrict__ x,
                                            float* __restrict__ out) {
    unsigned bid = blockIdx.x;
    if (bid % 5 == 0) {
        unsigned sid = bid / 5;
        unsigned lane = threadIdx.x & 31;
        unsigned b = sid * 8 + (threadIdx.x >> 5);
        unsigned count = g_cnt[b];
        if (count == 0) { if (lane == 0) g_dcnt[b] = 0; return; }
        if (count > MAXB) count = MAXB;   // statistically impossible; safety
        if (count <= 64) sort_bucket<2>(b, count, lane);
        else             sort_bucket<4>(b, count, lane);
    } else {
        unsigned xid = bid - bid / 5 - 1;          // 0 .. 32767
        xpool_chunk(xid * 256 + threadIdx.x, x, out);
    }
}

// fused single-pass 64K exclusive scan: 256 co-resident blocks + ticket + spin
__global__ __launch_bounds__(256) void k_scan() {
    __shared__ unsigned ws[8];
    __shared__ bool s_last;
    int tid = threadIdx.x;
    int lane = tid & 31, wid = tid >> 5;
    int i = blockIdx.x * 256 + tid;
    unsigned x = g_dcnt[i];

    unsigned v = x;
#pragma unroll
    for (int off = 16; off; off >>= 1) v += __shfl_down_sync(~0u, v, off);
    if (lane == 0) ws[wid] = v;
    __syncthreads();
    if (tid == 0) {
        unsigned s = 0;
#pragma unroll
        for (int w = 0; w < 8; w++) s += ws[w];
        g_part[blockIdx.x] = s;
        __threadfence();
        s_last = (atomicAdd(&g_done, 1u) == 255u);
    }
    __syncthreads();

    if (s_last) {
        unsigned px = g_part[tid];
        unsigned sv = px;
#pragma unroll
        for (int off = 1; off < 32; off <<= 1) {
            unsigned t = __shfl_up_sync(~0u, sv, off);
            if (lane >= off) sv += t;
        }
        if (lane == 31) ws[wid] = sv;
        __syncthreads();
        if (wid == 0 && lane < 8) {
            unsigned w = ws[lane];
#pragma unroll
            for (int off = 1; off < 8; off <<= 1) {
                unsigned t = __shfl_up_sync(0xffu, w, off);
                if (lane >= off) w += t;
            }
            ws[lane] = w;
        }
        __syncthreads();
        unsigned excl = sv - px + (wid > 0 ? ws[wid - 1] : 0u);
        g_partoff[tid] = excl;
        if (tid == 255) g_totalU = excl + px;
        __threadfence();
        if (tid == 0) atomicExch(&g_flag, 1u);
    } else {
        if (tid == 0) {
            while (atomicAdd(&g_flag, 0u) == 0u) __nanosleep(200);
        }
        __syncthreads();
        __threadfence();
    }

    __syncthreads();
    unsigned v2 = x;
#pragma unroll
    for (int off = 1; off < 32; off <<= 1) {
        unsigned t = __shfl_up_sync(~0u, v2, off);
        if (lane >= off) v2 += t;
    }
    if (lane == 31) ws[wid] = v2;
    __syncthreads();
    if (wid == 0 && lane < 8) {
        unsigned w = ws[lane];
#pragma unroll
        for (int off = 1; off < 8; off <<= 1) {
            unsigned t = __shfl_up_sync(0xffu, w, off);
            if (lane >= off) w += t;
        }
        ws[lane] = w;
    }
    __syncthreads();
    g_doff[i] = g_partoff[blockIdx.x] + v2 - x + (wid > 0 ? ws[wid - 1] : 0u);
}

// tail: runs (warp/bucket) + 512 grid-stride pad blocks
#define T_PAD     512
#define TAIL_GRID (8192 + T_PAD)
__global__ __launch_bounds__(256) void k_tail(const float* __restrict__ ea,
                                              float* __restrict__ out) {
    unsigned bid = blockIdx.x;
    if (bid < 8192) {
        unsigned lane = threadIdx.x & 31;
        unsigned b = bid * 8 + (threadIdx.x >> 5);
        unsigned count = g_cnt[b];
        if (count > MAXB) count = MAXB;
        if (count == 0) return;
        size_t start = (size_t)b * MAXB;
        unsigned doff = g_doff[b];
        for (unsigned i0 = 0; i0 < count; i0 += 32) {
            unsigned i = i0 + lane;
            if (i >= count) break;
            unsigned ms = g_ms[start + i];
            if (!(ms & 0x8000u)) continue;         // not a run head
            unsigned rank = doff + ((ms >> 8) & 0x7Fu);
            unsigned long long p = g_bkt[start + (ms & 0x7Fu)];
            unsigned key = (unsigned)(p >> 32);
            const float4* row = (const float4*)(ea + (size_t)(unsigned)p * DA);
            float4 a0 = row[0], a1 = row[1], a2 = row[2], a3 = row[3];
            unsigned j = i + 1;
            while (j < count) {
                unsigned ms2 = g_ms[start + j];
                if (ms2 & 0x8000u) break;
                unsigned long long p2 = g_bkt[start + (ms2 & 0x7Fu)];
                const float4* r2 = (const float4*)(ea + (size_t)(unsigned)p2 * DA);
                float4 b0 = r2[0], b1 = r2[1], b2 = r2[2], b3 = r2[3];
                a0.x += b0.x; a0.y += b0.y; a0.z += b0.z; a0.w += b0.w;
                a1.x += b1.x; a1.y += b1.y; a1.z += b1.z; a1.w += b1.w;
                a2.x += b2.x; a2.y += b2.y; a2.z += b2.z; a2.w += b2.w;
                a3.x += b3.x; a3.y += b3.y; a3.z += b3.z; a3.w += b3.w;
                j++;
            }
            float4* eao = (float4*)(out + EA_OFF + (size_t)rank * DA);
            eao[0] = a0; eao[1] = a1; eao[2] = a2; eao[3] = a3;
            out[EI_OFF + rank]      = (float)(key >> 16);
            out[EI_OFF + EE + rank] = (float)(key & 0xFFFFu);
        }
    } else {
        unsigned U = g_totalU;
        unsigned base = (bid - 8192) * 256 + threadIdx.x;
        for (unsigned r = base; r < EE; r += T_PAD * 256) {
            if (r < U) continue;
            out[EI_OFF + r]      = 65536.0f;
            out[EI_OFF + EE + r] = 0.0f;
            float4 z = {0, 0, 0, 0};
            float4* eao = (float4*)(out + EA_OFF + (size_t)r * DA);
            eao[0] = z; eao[1] = z; eao[2] = z; eao[3] = z;
        }
    }
}

// ---------------- launch ------------------------------------------------------

extern "C" void kernel_launch(void* const* d_in, const int* in_sizes, int n_in,
                              void* d_out, int out_size) {
    const float* x  = (const float*)d_in[0];
    const float* ea = (const float*)d_in[1];
    const void*  ei = d_in[2];
    float* out = (float*)d_out;

    k_init<<<256, 256>>>((const int2*)ei);
    k_p1<<<P1_GRID, 256>>>(ei, out);
    k_p2<<<P2_GRID, 256>>>(x, out);
    k_scan<<<256, 256>>>();
    k_tail<<<TAIL_GRID, 256>>>(ea, out);
}

// round 12
// speedup vs baseline: 1.0004x; 1.0004x over previous
#include <cuda_runtime.h>
#include <cuda_bf16.h>
#include <cstdint>

// Problem constants
#define NN      131072
#define FF      512
#define EE      2097152
#define DA      16
#define NPOOL   65536
#define FP      256
#define NB      65536       // buckets = pooled row (key >> 16)
#define MAXB    128         // max bucket size (Poisson mean 32)
#define NSLOT   ((unsigned)NB * MAXB)

// Output layout (float elements, single concatenated array)
#define X_OFF   0ull
#define EI_OFF  16777216ull
#define EA_OFF  (EI_OFF + 2ull*EE)
#define BP_OFF  (EA_OFF + (unsigned long long)EE*DA)

// ---------------- scratch ----------------------------------------------------
__device__ unsigned long long  g_bkt[NSLOT];   // 64 MB fixed slots: (key<<32)|edge
__device__ unsigned short      g_ms[NSLOT];    // 16 MB: head<<15 | lrank<<8 | slot
__device__ unsigned            g_cnt[NB];
__device__ unsigned            g_dcnt[NB];
__device__ unsigned            g_doff[NB];
__device__ unsigned            g_part[256];
__device__ unsigned            g_partoff[256];
__device__ unsigned            g_totalU;
__device__ unsigned            g_done;
__device__ unsigned            g_done2;
__device__ unsigned            g_flag;
__device__ int                 g_is32;

// ---------------- helpers -----------------------------------------------------

__device__ __forceinline__ void xpool_chunk(unsigned t, const float* __restrict__ x,
                                            float* __restrict__ out) {
    if (t >= NPOOL * (FP / 2)) return;
    unsigned n  = t >> 7;
    unsigned fq = t & 127;
    const float4* r0 = (const float4*)(x + (size_t)(2 * n) * FF)     + fq;
    const float4* r1 = (const float4*)(x + (size_t)(2 * n + 1) * FF) + fq;
    float4 a = *r0, b = *r1;
    float2 o;
    o.x = 0.25f * ((a.x + a.y) + (b.x + b.y));
    o.y = 0.25f * ((a.z + a.w) + (b.z + b.w));
    *(float2*)(out + X_OFF + (size_t)n * FP + 2 * fq) = o;
}

// ---- warp-level bitonic sort on 32-bit items, zero barriers -----------------
template<int NR>
__device__ __forceinline__ void warp_bitonic32(unsigned (&v)[NR], unsigned lane) {
    const unsigned N = NR * 32;
#pragma unroll
    for (unsigned k = 2; k <= N; k <<= 1) {
#pragma unroll
        for (unsigned j = N >> 1; j > 0; j >>= 1) {
            if (j >= k) continue;   // compile-time pruned
            if (j >= 32) {
                unsigned rj = j >> 5;
#pragma unroll
                for (int r = 0; r < NR; r++) {
                    if ((r & (int)rj) == 0 && (r ^ (int)rj) < NR) {
                        int r2 = r ^ (int)rj;
                        unsigned ia = r * 32 + lane;
                        bool up = ((ia & k) == 0);
                        unsigned a = v[r], b = v[r2];
                        if ((a > b) == up) { v[r] = b; v[r2] = a; }
                    }
                }
            } else {
#pragma unroll
                for (int r = 0; r < NR; r++) {
                    unsigned i = r * 32 + lane;
                    unsigned x = v[r];
                    unsigned y = __shfl_xor_sync(~0u, x, j);
                    bool up = ((i & k) == 0);
                    bool keepmin = (((lane & j) == 0) == up);
                    v[r] = keepmin ? (x < y ? x : y) : (x > y ? x : y);
                }
            }
        }
    }
}

template<int NR>
__device__ __forceinline__ void sort_bucket(unsigned b, unsigned count, unsigned lane) {
    size_t start = (size_t)b * MAXB;
    unsigned v[NR];
#pragma unroll
    for (int r = 0; r < NR; r++) {
        unsigned i = r * 32 + lane;
        if (i < count) {
            unsigned key = (unsigned)(g_bkt[start + i] >> 32);
            v[r] = ((key & 0xFFFFu) << 7) | i;     // col<<7 | slot
        } else v[r] = 0xFFFFFFFFu;
    }
    warp_bitonic32<NR>(v, lane);

    unsigned mask[NR];
    unsigned prev_last = 0xFFFFFFFFu;
#pragma unroll
    for (int r = 0; r < NR; r++) {
        unsigned p = __shfl_up_sync(~0u, v[r], 1);
        unsigned last = __shfl_sync(~0u, v[r], 31);
        if (lane == 0) p = prev_last;
        unsigned i = r * 32 + lane;
        bool head = (i < count) && ((i == 0) || ((p >> 7) != (v[r] >> 7)));
        mask[r] = __ballot_sync(~0u, head);
        prev_last = last;
    }
    unsigned base = 0;
#pragma unroll
    for (int r = 0; r < NR; r++) {
        unsigned i = r * 32 + lane;
        if (i < count) {
            unsigned head = (mask[r] >> lane) & 1u;
            unsigned lr = base + __popc(mask[r] & ((1u << lane) - 1u));
            g_ms[start + i] = (unsigned short)((head << 15) | (lr << 8) | (v[r] & 0x7Fu));
        }
        base += __popc(mask[r]);
    }
    if (lane == 0) g_dcnt[b] = base;
}

// ---------------- kernels ----------------------------------------------------

// init: zero g_cnt + tickets; block 0 warp 0 sniffs edge_index dtype
__global__ __launch_bounds__(256) void k_init(const int2* __restrict__ ei) {
    unsigned i = blockIdx.x * 256 + threadIdx.x;
    g_cnt[i] = 0;
    if (i == 0) { g_done = 0; g_done2 = 0; g_flag = 0; }
    if (blockIdx.x == 0 && threadIdx.x < 32) {
        unsigned lane = threadIdx.x;
        bool nz = false;
#pragma unroll
        for (int k = 0; k < 8; k++) nz |= (ei[lane * 8 + k].y != 0);
        unsigned m = __ballot_sync(~0u, nz);
        if (lane == 0) g_is32 = (m != 0) ? 1 : 0;
    }
}

// K1 (R10-proven): 1-in-3 scatter, 2-in-3 first half of xpool; extra blocks batch
#define P1_MAIN (8192 * 3)
#define P1_GRID (P1_MAIN + 256)
__global__ __launch_bounds__(256) void k_p1(const void* __restrict__ eiv,
                                            const float* __restrict__ x,
                                            float* __restrict__ out) {
    unsigned bid = blockIdx.x;
    if (bid >= P1_MAIN) {                           // batch_pooled
        unsigned n = (bid - P1_MAIN) * 256 + threadIdx.x;
        if (n < NPOOL) out[BP_OFF + n] = (float)(n >> 10);
        return;
    }
    if (bid % 3 == 0) {
        unsigned e = (bid / 3) * 256 + threadIdx.x;
        if (e >= EE) return;
        unsigned r, c;
        if (g_is32) {
            const int* ei = (const int*)eiv;
            r = (unsigned)ei[e]; c = (unsigned)ei[EE + e];
        } else {
            const long long* ei = (const long long*)eiv;
            r = (unsigned)ei[e]; c = (unsigned)ei[EE + e];
        }
        unsigned key = ((r >> 1) << 16) | (c >> 1);
        unsigned b = key >> 16;
        unsigned pos = atomicAdd(&g_cnt[b], 1u);
        if (pos < MAXB)
            g_bkt[(size_t)b * MAXB + pos] = ((unsigned long long)key << 32) | (unsigned)e;
    } else {
        unsigned xid = bid - bid / 3 - 1;          // 0 .. 16383
        xpool_chunk(xid * 256 + threadIdx.x, x, out);
    }
}

// K2 (R10-proven): 1-in-3 sort (8 buckets/block), 2-in-3 second half of xpool
#define P2_GRID (8192 * 3)
__global__ __launch_bounds__(256) void k_p2(const float* __restrict__ x,
                                            float* __restrict__ out) {
    unsigned bid = blockIdx.x;
    if (bid % 3 == 0) {
        unsigned lane = threadIdx.x & 31;
        unsigned b = (bid / 3) * 8 + (threadIdx.x >> 5);
        unsigned count = g_cnt[b];
        if (count == 0) { if (lane == 0) g_dcnt[b] = 0; return; }
        if (count > MAXB) count = MAXB;   // statistically impossible; safety
        if (count <= 64) sort_bucket<2>(b, count, lane);
        else             sort_bucket<4>(b, count, lane);
    } else {
        unsigned xid = (bid - bid / 3 - 1) + 16384; // 16384 .. 32767
        xpool_chunk(xid * 256 + threadIdx.x, x, out);
    }
}

// scan body, executed by tail blocks 0..255 (first wave, guaranteed resident)
__device__ __forceinline__ void scan_chunk(unsigned chunk) {
    __shared__ unsigned ws[8];
    __shared__ bool s_last;
    int tid = threadIdx.x;
    int lane = tid & 31, wid = tid >> 5;
    int i = chunk * 256 + tid;
    unsigned x = g_dcnt[i];

    unsigned v = x;
#pragma unroll
    for (int off = 16; off; off >>= 1) v += __shfl_down_sync(~0u, v, off);
    if (lane == 0) ws[wid] = v;
    __syncthreads();
    if (tid == 0) {
        unsigned s = 0;
#pragma unroll
        for (int w = 0; w < 8; w++) s += ws[w];
        g_part[chunk] = s;
        __threadfence();
        s_last = (atomicAdd(&g_done, 1u) == 255u);
    }
    __syncthreads();

    if (s_last) {
        unsigned px = g_part[tid];
        unsigned sv = px;
#pragma unroll
        for (int off = 1; off < 32; off <<= 1) {
            unsigned t = __shfl_up_sync(~0u, sv, off);
            if (lane >= off) sv += t;
        }
        if (lane == 31) ws[wid] = sv;
        __syncthreads();
        if (wid == 0 && lane < 8) {
            unsigned w = ws[lane];
#pragma unroll
            for (int off = 1; off < 8; off <<= 1) {
                unsigned t = __shfl_up_sync(0xffu, w, off);
                if (lane >= off) w += t;
            }
            ws[lane] = w;
        }
        __syncthreads();
        unsigned excl = sv - px + (wid > 0 ? ws[wid - 1] : 0u);
        g_partoff[tid] = excl;
        if (tid == 255) g_totalU = excl + px;
        __threadfence();
        if (tid == 0) atomicExch(&g_flag, 1u);
    } else {
        if (tid == 0) {
            while (atomicAdd(&g_flag, 0u) == 0u) __nanosleep(100);
        }
        __syncthreads();
        __threadfence();
    }

    __syncthreads();
    unsigned v2 = x;
#pragma unroll
    for (int off = 1; off < 32; off <<= 1) {
        unsigned t = __shfl_up_sync(~0u, v2, off);
        if (lane >= off) v2 += t;
    }
    if (lane == 31) ws[wid] = v2;
    __syncthreads();
    if (wid == 0 && lane < 8) {
        unsigned w = ws[lane];
#pragma unroll
        for (int off = 1; off < 8; off <<= 1) {
            unsigned t = __shfl_up_sync(0xffu, w, off);
            if (lane >= off) w += t;
        }
        ws[lane] = w;
    }
    __syncthreads();
    g_doff[i] = g_partoff[chunk] + v2 - x + (wid > 0 ? ws[wid - 1] : 0u);
    __threadfence();
    __syncthreads();
    if (tid == 0) atomicAdd(&g_done2, 1u);
}

// tail: blocks 0..255 run scan first; all blocks gate on scan completion,
// then runs (warp/bucket) + 512 grid-stride pad blocks
#define T_PAD     512
#define TAIL_GRID (8192 + T_PAD)
__global__ __launch_bounds__(256) void k_tail(const float* __restrict__ ea,
                                              float* __restrict__ out) {
    unsigned bid = blockIdx.x;
    if (bid < 256) scan_chunk(bid);

    // gate: wait for all 256 doff chunks
    if (threadIdx.x == 0) {
        while (atomicAdd(&g_done2, 0u) < 256u) __nanosleep(100);
    }
    __syncthreads();
    __threadfence();

    if (bid < 8192) {
        unsigned lane = threadIdx.x & 31;
        unsigned b = bid * 8 + (threadIdx.x >> 5);
        unsigned count = g_cnt[b];
        if (count > MAXB) count = MAXB;
        if (count == 0) return;
        size_t start = (size_t)b * MAXB;
        unsigned doff = g_doff[b];
        for (unsigned i0 = 0; i0 < count; i0 += 32) {
            unsigned i = i0 + lane;
            if (i >= count) break;
            unsigned ms = g_ms[start + i];
            if (!(ms & 0x8000u)) continue;         // not a run head
            unsigned rank = doff + ((ms >> 8) & 0x7Fu);
            unsigned long long p = g_bkt[start + (ms & 0x7Fu)];
            unsigned key = (unsigned)(p >> 32);
            const float4* row = (const float4*)(ea + (size_t)(unsigned)p * DA);
            float4 a0 = row[0], a1 = row[1], a2 = row[2], a3 = row[3];
            unsigned j = i + 1;
            while (j < count) {
                unsigned ms2 = g_ms[start + j];
                if (ms2 & 0x8000u) break;
                unsigned long long p2 = g_bkt[start + (ms2 & 0x7Fu)];
                const float4* r2 = (const float4*)(ea + (size_t)(unsigned)p2 * DA);
                float4 b0 = r2[0], b1 = r2[1], b2 = r2[2], b3 = r2[3];
                a0.x += b0.x; a0.y += b0.y; a0.z += b0.z; a0.w += b0.w;
                a1.x += b1.x; a1.y += b1.y; a1.z += b1.z; a1.w += b1.w;
                a2.x += b2.x; a2.y += b2.y; a2.z += b2.z; a2.w += b2.w;
                a3.x += b3.x; a3.y += b3.y; a3.z += b3.z; a3.w += b3.w;
                j++;
            }
            float4* eao = (float4*)(out + EA_OFF + (size_t)rank * DA);
            eao[0] = a0; eao[1] = a1; eao[2] = a2; eao[3] = a3;
            out[EI_OFF + rank]      = (float)(key >> 16);
            out[EI_OFF + EE + rank] = (float)(key & 0xFFFFu);
        }
    } else {
        unsigned U = g_totalU;
        unsigned base = (bid - 8192) * 256 + threadIdx.x;
        for (unsigned r = base; r < EE; r += T_PAD * 256) {
            if (r < U) continue;
            out[EI_OFF + r]      = 65536.0f;
            out[EI_OFF + EE + r] = 0.0f;
            float4 z = {0, 0, 0, 0};
            float4* eao = (float4*)(out + EA_OFF + (size_t)r * DA);
            eao[0] = z; eao[1] = z; eao[2] = z; eao[3] = z;
        }
    }
}

// ---------------- launch ------------------------------------------------------

extern "C" void kernel_launch(void* const* d_in, const int* in_sizes, int n_in,
                              void* d_out, int out_size) {
    const float* x  = (const float*)d_in[0];
    const float* ea = (const float*)d_in[1];
    const void*  ei = d_in[2];
    float* out = (float*)d_out;

    k_init<<<256, 256>>>((const int2*)ei);
    k_p1<<<P1_GRID, 256>>>(ei, x, out);
    k_p2<<<P2_GRID, 256>>>(x, out);
    k_tail<<<TAIL_GRID, 256>>>(ea, out);
}

// round 13
// speedup vs baseline: 1.0622x; 1.0618x over previous
#include <cuda_runtime.h>
#include <cuda_bf16.h>
#include <cstdint>

// Problem constants
#define NN      131072
#define FF      512
#define EE      2097152
#define DA      16
#define NPOOL   65536
#define FP      256
#define NB      65536       // buckets = pooled row (key >> 16)
#define MAXB    128         // max bucket size (Poisson mean 32)
#define NSLOT   ((unsigned)NB * MAXB)

// Output layout (float elements, single concatenated array)
#define X_OFF   0ull
#define EI_OFF  16777216ull
#define EA_OFF  (EI_OFF + 2ull*EE)
#define BP_OFF  (EA_OFF + (unsigned long long)EE*DA)

// ---------------- scratch ----------------------------------------------------
__device__ unsigned long long  g_bkt[NSLOT];   // 64 MB fixed slots: (key<<32)|edge
__device__ unsigned long long  g_srt[NSLOT];   // 64 MB: col16<<32|head<<28|lrank<<21|edge21
__device__ unsigned            g_cnt[NB];
__device__ unsigned            g_dcnt[NB];
__device__ unsigned            g_doff[NB];
__device__ unsigned            g_part[256];
__device__ unsigned            g_partoff[256];
__device__ unsigned            g_totalU;
__device__ unsigned            g_done;
__device__ unsigned            g_flag;
__device__ int                 g_is32;

// ---------------- helpers -----------------------------------------------------

__device__ __forceinline__ void xpool_chunk(unsigned t, const float* __restrict__ x,
                                            float* __restrict__ out) {
    if (t >= NPOOL * (FP / 2)) return;
    unsigned n  = t >> 7;
    unsigned fq = t & 127;
    const float4* r0 = (const float4*)(x + (size_t)(2 * n) * FF)     + fq;
    const float4* r1 = (const float4*)(x + (size_t)(2 * n + 1) * FF) + fq;
    float4 a = *r0, b = *r1;
    float2 o;
    o.x = 0.25f * ((a.x + a.y) + (b.x + b.y));
    o.y = 0.25f * ((a.z + a.w) + (b.z + b.w));
    *(float2*)(out + X_OFF + (size_t)n * FP + 2 * fq) = o;
}

// ---- warp-level bitonic sort on 32-bit items, zero barriers -----------------
template<int NR>
__device__ __forceinline__ void warp_bitonic32(unsigned (&v)[NR], unsigned lane) {
    const unsigned N = NR * 32;
#pragma unroll
    for (unsigned k = 2; k <= N; k <<= 1) {
#pragma unroll
        for (unsigned j = N >> 1; j > 0; j >>= 1) {
            if (j >= k) continue;   // compile-time pruned
            if (j >= 32) {
                unsigned rj = j >> 5;
#pragma unroll
                for (int r = 0; r < NR; r++) {
                    if ((r & (int)rj) == 0 && (r ^ (int)rj) < NR) {
                        int r2 = r ^ (int)rj;
                        unsigned ia = r * 32 + lane;
                        bool up = ((ia & k) == 0);
                        unsigned a = v[r], b = v[r2];
                        if ((a > b) == up) { v[r] = b; v[r2] = a; }
                    }
                }
            } else {
#pragma unroll
                for (int r = 0; r < NR; r++) {
                    unsigned i = r * 32 + lane;
                    unsigned x = v[r];
                    unsigned y = __shfl_xor_sync(~0u, x, j);
                    bool up = ((i & k) == 0);
                    bool keepmin = (((lane & j) == 0) == up);
                    v[r] = keepmin ? (x < y ? x : y) : (x > y ? x : y);
                }
            }
        }
    }
}

template<int NR>
__device__ __forceinline__ void sort_bucket(unsigned b, unsigned count, unsigned lane) {
    size_t start = (size_t)b * MAXB;
    unsigned v[NR];
#pragma unroll
    for (int r = 0; r < NR; r++) {
        unsigned i = r * 32 + lane;
        if (i < count) {
            unsigned key = (unsigned)(g_bkt[start + i] >> 32);
            v[r] = ((key & 0xFFFFu) << 7) | i;     // col<<7 | slot
        } else v[r] = 0xFFFFFFFFu;
    }
    warp_bitonic32<NR>(v, lane);

    unsigned mask[NR];
    unsigned prev_last = 0xFFFFFFFFu;
#pragma unroll
    for (int r = 0; r < NR; r++) {
        unsigned p = __shfl_up_sync(~0u, v[r], 1);
        unsigned last = __shfl_sync(~0u, v[r], 31);
        if (lane == 0) p = prev_last;
        unsigned i = r * 32 + lane;
        bool head = (i < count) && ((i == 0) || ((p >> 7) != (v[r] >> 7)));
        mask[r] = __ballot_sync(~0u, head);
        prev_last = last;
    }
    unsigned base = 0;
#pragma unroll
    for (int r = 0; r < NR; r++) {
        unsigned i = r * 32 + lane;
        if (i < count) {
            unsigned head = (mask[r] >> lane) & 1u;
            unsigned lr = base + __popc(mask[r] & ((1u << lane) - 1u));
            unsigned slot = v[r] & 0x7Fu;
            unsigned col  = v[r] >> 7;                    // 16 bits
            unsigned edge = (unsigned)g_bkt[start + slot]; // low word = edge idx (L1 hit)
            g_srt[start + i] = ((unsigned long long)col << 32)
                             | ((unsigned long long)head << 28)
                             | ((unsigned long long)lr << 21)
                             | edge;
        }
        base += __popc(mask[r]);
    }
    if (lane == 0) g_dcnt[b] = base;
}

// ---------------- kernels ----------------------------------------------------

// init: zero g_cnt + tickets; block 0 warp 0 sniffs edge_index dtype
__global__ __launch_bounds__(256) void k_init(const int2* __restrict__ ei) {
    unsigned i = blockIdx.x * 256 + threadIdx.x;
    g_cnt[i] = 0;
    if (i == 0) { g_done = 0; g_flag = 0; }
    if (blockIdx.x == 0 && threadIdx.x < 32) {
        unsigned lane = threadIdx.x;
        bool nz = false;
#pragma unroll
        for (int k = 0; k < 8; k++) nz |= (ei[lane * 8 + k].y != 0);
        unsigned m = __ballot_sync(~0u, nz);
        if (lane == 0) g_is32 = (m != 0) ? 1 : 0;
    }
}

// K1 (R10-proven): 1-in-3 scatter, 2-in-3 first half of xpool; extra blocks batch
#define P1_MAIN (8192 * 3)
#define P1_GRID (P1_MAIN + 256)
__global__ __launch_bounds__(256) void k_p1(const void* __restrict__ eiv,
                                            const float* __restrict__ x,
                                            float* __restrict__ out) {
    unsigned bid = blockIdx.x;
    if (bid >= P1_MAIN) {                           // batch_pooled
        unsigned n = (bid - P1_MAIN) * 256 + threadIdx.x;
        if (n < NPOOL) out[BP_OFF + n] = (float)(n >> 10);
        return;
    }
    if (bid % 3 == 0) {
        unsigned e = (bid / 3) * 256 + threadIdx.x;
        if (e >= EE) return;
        unsigned r, c;
        if (g_is32) {
            const int* ei = (const int*)eiv;
            r = (unsigned)ei[e]; c = (unsigned)ei[EE + e];
        } else {
            const long long* ei = (const long long*)eiv;
            r = (unsigned)ei[e]; c = (unsigned)ei[EE + e];
        }
        unsigned key = ((r >> 1) << 16) | (c >> 1);
        unsigned b = key >> 16;
        unsigned pos = atomicAdd(&g_cnt[b], 1u);
        if (pos < MAXB)
            g_bkt[(size_t)b * MAXB + pos] = ((unsigned long long)key << 32) | (unsigned)e;
    } else {
        unsigned xid = bid - bid / 3 - 1;          // 0 .. 16383
        xpool_chunk(xid * 256 + threadIdx.x, x, out);
    }
}

// K2 (R10-proven): 1-in-3 sort (8 buckets/block), 2-in-3 second half of xpool
#define P2_GRID (8192 * 3)
__global__ __launch_bounds__(256) void k_p2(const float* __restrict__ x,
                                            float* __restrict__ out) {
    unsigned bid = blockIdx.x;
    if (bid % 3 == 0) {
        unsigned lane = threadIdx.x & 31;
        unsigned b = (bid / 3) * 8 + (threadIdx.x >> 5);
        unsigned count = g_cnt[b];
        if (count == 0) { if (lane == 0) g_dcnt[b] = 0; return; }
        if (count > MAXB) count = MAXB;   // statistically impossible; safety
        if (count <= 64) sort_bucket<2>(b, count, lane);
        else             sort_bucket<4>(b, count, lane);
    } else {
        unsigned xid = (bid - bid / 3 - 1) + 16384; // 16384 .. 32767
        xpool_chunk(xid * 256 + threadIdx.x, x, out);
    }
}

// fused single-pass 64K exclusive scan: 256 co-resident blocks + ticket + spin
__global__ __launch_bounds__(256) void k_scan() {
    __shared__ unsigned ws[8];
    __shared__ bool s_last;
    int tid = threadIdx.x;
    int lane = tid & 31, wid = tid >> 5;
    int i = blockIdx.x * 256 + tid;
    unsigned x = g_dcnt[i];

    unsigned v = x;
#pragma unroll
    for (int off = 16; off; off >>= 1) v += __shfl_down_sync(~0u, v, off);
    if (lane == 0) ws[wid] = v;
    __syncthreads();
    if (tid == 0) {
        unsigned s = 0;
#pragma unroll
        for (int w = 0; w < 8; w++) s += ws[w];
        g_part[blockIdx.x] = s;
        __threadfence();
        s_last = (atomicAdd(&g_done, 1u) == 255u);
    }
    __syncthreads();

    if (s_last) {
        unsigned px = g_part[tid];
        unsigned sv = px;
#pragma unroll
        for (int off = 1; off < 32; off <<= 1) {
            unsigned t = __shfl_up_sync(~0u, sv, off);
            if (lane >= off) sv += t;
        }
        if (lane == 31) ws[wid] = sv;
        __syncthreads();
        if (wid == 0 && lane < 8) {
            unsigned w = ws[lane];
#pragma unroll
            for (int off = 1; off < 8; off <<= 1) {
                unsigned t = __shfl_up_sync(0xffu, w, off);
                if (lane >= off) w += t;
            }
            ws[lane] = w;
        }
        __syncthreads();
        unsigned excl = sv - px + (wid > 0 ? ws[wid - 1] : 0u);
        g_partoff[tid] = excl;
        if (tid == 255) g_totalU = excl + px;
        __threadfence();
        if (tid == 0) atomicExch(&g_flag, 1u);
    } else {
        if (tid == 0) {
            while (atomicAdd(&g_flag, 0u) == 0u) __nanosleep(200);
        }
        __syncthreads();
        __threadfence();
    }

    __syncthreads();
    unsigned v2 = x;
#pragma unroll
    for (int off = 1; off < 32; off <<= 1) {
        unsigned t = __shfl_up_sync(~0u, v2, off);
        if (lane >= off) v2 += t;
    }
    if (lane == 31) ws[wid] = v2;
    __syncthreads();
    if (wid == 0 && lane < 8) {
        unsigned w = ws[lane];
#pragma unroll
        for (int off = 1; off < 8; off <<= 1) {
            unsigned t = __shfl_up_sync(0xffu, w, off);
            if (lane >= off) w += t;
        }
        ws[lane] = w;
    }
    __syncthreads();
    g_doff[i] = g_partoff[blockIdx.x] + v2 - x + (wid > 0 ? ws[wid - 1] : 0u);
}

// tail: runs (warp/bucket, 2-deep chain via g_srt) + 512 grid-stride pad blocks
#define T_PAD     512
#define TAIL_GRID (8192 + T_PAD)
__global__ __launch_bounds__(256) void k_tail(const float* __restrict__ ea,
                                              float* __restrict__ out) {
    unsigned bid = blockIdx.x;
    if (bid < 8192) {
        unsigned lane = threadIdx.x & 31;
        unsigned b = bid * 8 + (threadIdx.x >> 5);
        unsigned count = g_cnt[b];
        if (count > MAXB) count = MAXB;
        if (count == 0) return;
        size_t start = (size_t)b * MAXB;
        unsigned doff = g_doff[b];
        for (unsigned i0 = 0; i0 < count; i0 += 32) {
            unsigned i = i0 + lane;
            if (i >= count) break;
            unsigned long long s = g_srt[start + i];     // coalesced 8B
            if (!(s & (1ull << 28))) continue;           // not a run head
            unsigned rank = doff + (((unsigned)(s >> 21)) & 0x7Fu);
            unsigned edge = (unsigned)s & 0x1FFFFFu;
            const float4* row = (const float4*)(ea + (size_t)edge * DA);
            float4 a0 = row[0], a1 = row[1], a2 = row[2], a3 = row[3];
            unsigned j = i + 1;
            while (j < count) {
                unsigned long long s2 = g_srt[start + j];
                if (s2 & (1ull << 28)) break;
                unsigned e2 = (unsigned)s2 & 0x1FFFFFu;
                const float4* r2 = (const float4*)(ea + (size_t)e2 * DA);
                float4 b0 = r2[0], b1 = r2[1], b2 = r2[2], b3 = r2[3];
                a0.x += b0.x; a0.y += b0.y; a0.z += b0.z; a0.w += b0.w;
                a1.x += b1.x; a1.y += b1.y; a1.z += b1.z; a1.w += b1.w;
                a2.x += b2.x; a2.y += b2.y; a2.z += b2.z; a2.w += b2.w;
                a3.x += b3.x; a3.y += b3.y; a3.z += b3.z; a3.w += b3.w;
                j++;
            }
            float4* eao = (float4*)(out + EA_OFF + (size_t)rank * DA);
            eao[0] = a0; eao[1] = a1; eao[2] = a2; eao[3] = a3;
            out[EI_OFF + rank]      = (float)b;
            out[EI_OFF + EE + rank] = (float)(unsigned)(s >> 32);
        }
    } else {
        unsigned U = g_totalU;
        unsigned base = (bid - 8192) * 256 + threadIdx.x;
        for (unsigned r = base; r < EE; r += T_PAD * 256) {
            if (r < U) continue;
            out[EI_OFF + r]      = 65536.0f;
            out[EI_OFF + EE + r] = 0.0f;
            float4 z = {0, 0, 0, 0};
            float4* eao = (float4*)(out + EA_OFF + (size_t)r * DA);
            eao[0] = z; eao[1] = z; eao[2] = z; eao[3] = z;
        }
    }
}

// ---------------- launch ------------------------------------------------------

extern "C" void kernel_launch(void* const* d_in, const int* in_sizes, int n_in,
                              void* d_out, int out_size) {
    const float* x  = (const float*)d_in[0];
    const float* ea = (const float*)d_in[1];
    const void*  ei = d_in[2];
    float* out = (float*)d_out;

    k_init<<<256, 256>>>((const int2*)ei);
    k_p1<<<P1_GRID, 256>>>(ei, x, out);
    k_p2<<<P2_GRID, 256>>>(x, out);
    k_scan<<<256, 256>>>();
    k_tail<<<TAIL_GRID, 256>>>(ea, out);
}